// round 13
// baseline (speedup 1.0000x reference)
#include <cuda_runtime.h>
#include <cuda_bf16.h>
#include <math.h>

// Problem constants
#define BB   256
#define TT   1000
#define HH   64
#define GG   256   // 4*H
#define DIN  22
#define DH   128   // 2*H

typedef unsigned int u32;
typedef unsigned long long u64;

// Scratch (device globals; no runtime allocation allowed)
__device__ float g_xw[(size_t)2 * BB * TT * GG];            // [dir][b][t][g]
__device__ __nv_bfloat16 g_hbf_hi[(size_t)BB * TT * DH];    // h split hi [b][t][d]
__device__ __nv_bfloat16 g_hbf_lo[(size_t)BB * TT * DH];    // h split lo
__device__ __nv_bfloat16 g_wbf_hi[(size_t)6 * GG * DH];     // W_ih split hi [(l-1)*2+dir][g][k]
__device__ __nv_bfloat16 g_wbf_lo[(size_t)6 * GG * DH];

// ---- packed f32x2 helpers ----
__device__ __forceinline__ u64 pack2(float lo, float hi) {
    u64 r; asm("mov.b64 %0, {%1, %2};" : "=l"(r) : "f"(lo), "f"(hi)); return r;
}
__device__ __forceinline__ void unpack2(u64 v, float& lo, float& hi) {
    asm("mov.b64 {%0, %1}, %2;" : "=f"(lo), "=f"(hi) : "l"(v));
}
__device__ __forceinline__ u64 fma2(u64 a, u64 b, u64 c) {
    u64 d; asm("fma.rn.f32x2 %0, %1, %2, %3;" : "=l"(d) : "l"(a), "l"(b), "l"(c));
    return d;
}
__device__ __forceinline__ u64 shfl_add2(u64 v, int m) {
    float lo, hi; unpack2(v, lo, hi);
    float lo2 = __shfl_xor_sync(0xFFFFFFFFu, lo, m);
    float hi2 = __shfl_xor_sync(0xFFFFFFFFu, hi, m);
    return pack2(lo + lo2, hi + hi2);
}

__device__ __forceinline__ float ex2a(float x) {
    float y; asm("ex2.approx.f32 %0, %1;" : "=f"(y) : "f"(x)); return y;
}
__device__ __forceinline__ float rcpa(float x) {
    float y; asm("rcp.approx.f32 %0, %1;" : "=f"(y) : "f"(x)); return y;
}
#define L2E  1.4426950408889634f
__device__ __forceinline__ float fast_sig(float x) {
    return rcpa(1.0f + ex2a(-L2E * x));
}
__device__ __forceinline__ float fast_tanh(float x) {
    return fmaf(2.0f, rcpa(1.0f + ex2a(-2.0f * L2E * x)), -1.0f);
}
__device__ __forceinline__ void bf16split(float f, __nv_bfloat16& h, __nv_bfloat16& l) {
    h = __float2bfloat16(f);
    l = __float2bfloat16(f - __bfloat162float(h));
}

// ---- bf16 HMMA m16n8k16 (baseline PTX, sm_80+) ----
__device__ __forceinline__ void mma16816(
    float& d0, float& d1, float& d2, float& d3,
    u32 a0, u32 a1, u32 a2, u32 a3, u32 b0, u32 b1)
{
    asm volatile(
        "mma.sync.aligned.m16n8k16.row.col.f32.bf16.bf16.f32 "
        "{%0,%1,%2,%3}, {%4,%5,%6,%7}, {%8,%9}, {%0,%1,%2,%3};"
        : "+f"(d0), "+f"(d1), "+f"(d2), "+f"(d3)
        : "r"(a0), "r"(a1), "r"(a2), "r"(a3), "r"(b0), "r"(b1));
}

// ---------------------------------------------------------------------------
// W_ih bf16 hi/lo split prep. grid 6 blocks (ld = (l-1)*2+dir), 256 threads.
// ---------------------------------------------------------------------------
__global__ __launch_bounds__(256) void wsplit_kernel(
    const float* __restrict__ w)       // (3, 2, 256, 128)
{
    const int ld = blockIdx.x;
    const int g = threadIdx.x;
    const float* src = w + (size_t)ld * GG * DH + (size_t)g * DH;
    __nv_bfloat16* dh = g_wbf_hi + (size_t)ld * GG * DH + (size_t)g * DH;
    __nv_bfloat16* dl = g_wbf_lo + (size_t)ld * GG * DH + (size_t)g * DH;
#pragma unroll 4
    for (int k = 0; k < DH; k++) {
        __nv_bfloat16 h, l;
        bf16split(src[k], h, l);
        dh[k] = h; dl[k] = l;
    }
}

// ---------------------------------------------------------------------------
// Layer-0 input projection, t-split x4. grid (B, 2, 4), 256 threads. (fp32)
// ---------------------------------------------------------------------------
__global__ __launch_bounds__(256) void gemm0_kernel(
    const float* __restrict__ x,       // (B, 22, T)
    const float* __restrict__ w,       // (2, 256, 22)
    const float* __restrict__ bih,     // (4, 2, 256)
    const float* __restrict__ bhh)     // (4, 2, 256)
{
    const int b = blockIdx.x, dir = blockIdx.y, tch = blockIdx.z;
    const int g = threadIdx.x;
    __shared__ float xs[DIN][16];

    float wr[DIN];
#pragma unroll
    for (int d = 0; d < DIN; d++) wr[d] = w[(dir * GG + g) * DIN + d];
    const float bias = bih[dir * GG + g] + bhh[dir * GG + g];

    const float* xb = x + (size_t)b * DIN * TT;
    float* out = g_xw + ((size_t)(dir * BB + b)) * TT * GG;

    const int tbase = tch * 256;
    const int tend  = (tbase + 256 < TT) ? (tbase + 256) : TT;

    for (int tc = tbase; tc < tend; tc += 16) {
        for (int e = threadIdx.x; e < DIN * 16; e += 256) {
            int d = e >> 4, tt = e & 15;
            int t = tc + tt;
            xs[d][tt] = (t < TT) ? xb[d * TT + t] : 0.0f;
        }
        __syncthreads();
        float acc[16];
#pragma unroll
        for (int tt = 0; tt < 16; tt++) acc[tt] = bias;
#pragma unroll
        for (int d = 0; d < DIN; d++) {
            float wd = wr[d];
#pragma unroll
            for (int tt = 0; tt < 16; tt++) acc[tt] = fmaf(wd, xs[d][tt], acc[tt]);
        }
#pragma unroll
        for (int tt = 0; tt < 16; tt++) {
            int t = tc + tt;
            if (t < tend) out[(size_t)t * GG + g] = acc[tt];
        }
        __syncthreads();
    }
}

// ---------------------------------------------------------------------------
// Layers 1..3 input projection via bf16-split HMMA (mma.sync m16n8k16).
// grid (B, 2, 8): (batch, dir, t-chunk of 128). 256 threads, 2 blocks/SM.
// A = x (t x k, from smem, hi/lo), B = W (k x g col-major = W[g][k], from
// global prepped bf16, L2-resident). D = Xhi*Whi + Xlo*Whi + Xhi*Wlo.
// Warp tile 32t x 32g; 4 iterations (tpass x gpass). One barrier per block.
// smem X rows padded to 272B: fragment reads (8 rows x 4 words, row shift
// 4 banks) are conflict-free.
// ---------------------------------------------------------------------------
#define XROWB 272                      // bytes per t-row (128 bf16 + 8 pad)
#define OFF_XL2 (128 * XROWB)          // 34816
#define OFF_BI2 (2 * 128 * XROWB)      // 69632
#define MM_SMEM (OFF_BI2 + GG * 4)     // 70656 B

__global__ __launch_bounds__(256, 2) void gemm_mma_kernel(
    const float* __restrict__ bih,
    const float* __restrict__ bhh,
    int layer)
{
    extern __shared__ char smb[];
    float* bsm = (float*)(smb + OFF_BI2);

    const int b = blockIdx.x, dir = blockIdx.y, tch = blockIdx.z;
    const int tid = threadIdx.x;
    const int w8 = tid >> 5, lane = tid & 31;
    const int tw = w8 & 1;             // t subgroup (0..1)
    const int gw = w8 >> 1;            // gate subgroup (0..3)
    const int g4 = lane >> 2;          // groupID (0..7)
    const int t4 = lane & 3;           // thread-in-group

    const int tb = tch * 128;          // global t base of this chunk

    // Stage bias
    if (tid < GG)
        bsm[tid] = bih[(layer * 2 + dir) * GG + tid]
                 + bhh[(layer * 2 + dir) * GG + tid];

    // Stage X chunk (hi/lo) into smem rows [t][128 halves], 272B stride
    {
        const uint4* hip = (const uint4*)(g_hbf_hi + (size_t)b * TT * DH);
        const uint4* lop = (const uint4*)(g_hbf_lo + (size_t)b * TT * DH);
        // 128 rows x 16 uint4 per split = 2048 uint4 per split
        for (int e = tid; e < 2048; e += 256) {
            int r = e >> 4, q = e & 15;
            int t = tb + r;
            uint4 vh, vl;
            if (t < TT) {
                vh = hip[t * 16 + q];   // DH halves = 256B = 16 uint4
                vl = lop[t * 16 + q];
            } else {
                vh = make_uint4(0, 0, 0, 0); vl = vh;
            }
            *(uint4*)(smb + r * XROWB + q * 16) = vh;
            *(uint4*)(smb + OFF_XL2 + r * XROWB + q * 16) = vl;
        }
    }
    __syncthreads();

    const int ld = (layer - 1) * 2 + dir;
    const __nv_bfloat16* wh = g_wbf_hi + (size_t)ld * GG * DH;
    const __nv_bfloat16* wl = g_wbf_lo + (size_t)ld * GG * DH;
    float* outp = g_xw + ((size_t)(dir * BB + b)) * TT * GG;

#pragma unroll
    for (int it = 0; it < 4; it++) {
        const int tloc  = (it >> 1) * 64 + tw * 32;          // local t base
        const int gbase = (it & 1) * 128 + gw * 32;          // gate base

        float acc[2][4][4];
#pragma unroll
        for (int mt = 0; mt < 2; mt++)
#pragma unroll
            for (int nt = 0; nt < 4; nt++)
#pragma unroll
                for (int i = 0; i < 4; i++) acc[mt][nt][i] = 0.0f;

#pragma unroll
        for (int ks = 0; ks < 8; ks++) {
            const int cof = ks * 32 + t4 * 4;   // byte offset of k halves 2t4

            u32 ah[2][4], al[2][4];
#pragma unroll
            for (int mt = 0; mt < 2; mt++) {
                int r0 = tloc + mt * 16 + g4;
                const char* ph = smb + r0 * XROWB + cof;
                const char* pl = smb + OFF_XL2 + r0 * XROWB + cof;
                ah[mt][0] = *(const u32*)(ph);
                ah[mt][1] = *(const u32*)(ph + 8 * XROWB);
                ah[mt][2] = *(const u32*)(ph + 16);
                ah[mt][3] = *(const u32*)(ph + 8 * XROWB + 16);
                al[mt][0] = *(const u32*)(pl);
                al[mt][1] = *(const u32*)(pl + 8 * XROWB);
                al[mt][2] = *(const u32*)(pl + 16);
                al[mt][3] = *(const u32*)(pl + 8 * XROWB + 16);
            }

#pragma unroll
            for (int nt = 0; nt < 4; nt++) {
                int n = gbase + nt * 8 + g4;
                size_t wo = (size_t)n * DH + ks * 16 + 2 * t4;
                u32 bh0 = *(const u32*)(wh + wo);
                u32 bh1 = *(const u32*)(wh + wo + 8);
                u32 bl0 = *(const u32*)(wl + wo);
                u32 bl1 = *(const u32*)(wl + wo + 8);
#pragma unroll
                for (int mt = 0; mt < 2; mt++) {
                    mma16816(acc[mt][nt][0], acc[mt][nt][1],
                             acc[mt][nt][2], acc[mt][nt][3],
                             ah[mt][0], ah[mt][1], ah[mt][2], ah[mt][3],
                             bh0, bh1);
                    mma16816(acc[mt][nt][0], acc[mt][nt][1],
                             acc[mt][nt][2], acc[mt][nt][3],
                             al[mt][0], al[mt][1], al[mt][2], al[mt][3],
                             bh0, bh1);
                    mma16816(acc[mt][nt][0], acc[mt][nt][1],
                             acc[mt][nt][2], acc[mt][nt][3],
                             ah[mt][0], ah[mt][1], ah[mt][2], ah[mt][3],
                             bl0, bl1);
                }
            }
        }

        // Store with bias. D layout: c0 (t=g4, n=2t4), c1 (n=2t4+1),
        // c2 (t=g4+8, n=2t4), c3 (n=2t4+1).
#pragma unroll
        for (int mt = 0; mt < 2; mt++) {
#pragma unroll
            for (int nt = 0; nt < 4; nt++) {
                int n0 = gbase + nt * 8 + 2 * t4;
                float b0 = bsm[n0], b1 = bsm[n0 + 1];
                int tr0 = tb + tloc + mt * 16 + g4;
                int tr1 = tr0 + 8;
                if (tr0 < TT)
                    *(float2*)(outp + (size_t)tr0 * GG + n0) =
                        make_float2(acc[mt][nt][0] + b0, acc[mt][nt][1] + b1);
                if (tr1 < TT)
                    *(float2*)(outp + (size_t)tr1 * GG + n0) =
                        make_float2(acc[mt][nt][2] + b0, acc[mt][nt][3] + b1);
            }
        }
    }
}

// ---------------------------------------------------------------------------
// Recurrent scan (FROZEN math from R9); output bf16 hi/lo split.
// grid (B/2, 2), 256 threads, 2 blocks/SM, one barrier per step.
// ---------------------------------------------------------------------------
#define HROW 80
#define HBUF (2 * HROW)

__global__ __launch_bounds__(256, 2) void lstm_recur_kernel(
    const float* __restrict__ whh,     // (4, 2, 256, 64)
    int layer)
{
    __shared__ __align__(16) float hs2[2 * HBUF];    // double buffer

    const int dir = blockIdx.y;
    const int b0 = blockIdx.x * 2;
    const int tid = threadIdx.x;
    const int lane = tid & 31;
    const int j_lo = lane & 7;
    const int ks   = lane >> 3;          // k-slice 0..3
    const int j_hi = tid >> 5;           // warp 0..7
    const int j    = j_hi * 8 + j_lo;    // hidden unit 0..63

    u64 wg[4][8];
    {
        const float* wb = whh + (size_t)(layer * 2 + dir) * GG * HH;
#pragma unroll
        for (int g = 0; g < 4; g++) {
            const float2* wr = (const float2*)(wb + ((size_t)(g * 64 + j)) * HH + ks * 16);
#pragma unroll
            for (int p = 0; p < 8; p++) {
                float2 v = wr[p];
                wg[g][p] = pack2(v.x, v.y);
            }
        }
    }

    for (int e = tid; e < 2 * HBUF; e += 256) hs2[e] = 0.0f;

    const bool act = (ks < 2);
    const int bl = ks & 1;
    const float* xwp = g_xw + ((size_t)(dir * BB + b0 + bl)) * TT * GG + j;
    __nv_bfloat16* hop = g_hbf_hi + ((size_t)(b0 + bl) * TT) * DH + dir * HH + j;
    __nv_bfloat16* lopw = g_hbf_lo + ((size_t)(b0 + bl) * TT) * DH + dir * HH + j;
    float c = 0.0f;

    __syncthreads();

    float nx_i = 0.f, nx_f = 0.f, nx_g = 0.f, nx_o = 0.f;
    if (act) {
        int t0 = dir ? (TT - 1) : 0;
        const float* xp = xwp + (size_t)t0 * GG;
        nx_i = xp[0]; nx_f = xp[64]; nx_g = xp[128]; nx_o = xp[192];
    }

    const int rdoff = ks * 20;
    const int wroff = bl * HROW + (j >> 4) * 20 + (j & 15);

    for (int s = 0; s < TT; s++) {
        const int t = dir ? (TT - 1 - s) : s;
        float cx_i = nx_i, cx_f = nx_f, cx_g = nx_g, cx_o = nx_o;
        if (act && s + 1 < TT) {
            int tn = dir ? (t - 1) : (t + 1);
            const float* xp = xwp + (size_t)tn * GG;
            nx_i = xp[0]; nx_f = xp[64]; nx_g = xp[128]; nx_o = xp[192];
        }

        const float* hb = hs2 + ((s + 1) & 1) * HBUF + rdoff;
        const ulonglong2* h0p = (const ulonglong2*)hb;
        const ulonglong2* h1p = (const ulonglong2*)(hb + HROW);

        u64 z = pack2(0.f, 0.f);
        u64 acc[4][2];
#pragma unroll
        for (int g = 0; g < 4; g++) { acc[g][0] = z; acc[g][1] = z; }

#pragma unroll
        for (int q = 0; q < 4; q++) {
            ulonglong2 h0 = h0p[q];
            ulonglong2 h1 = h1p[q];
#pragma unroll
            for (int g = 0; g < 4; g++) {
                acc[g][0] = fma2(h0.x, wg[g][2 * q],     acc[g][0]);
                acc[g][0] = fma2(h0.y, wg[g][2 * q + 1], acc[g][0]);
                acc[g][1] = fma2(h1.x, wg[g][2 * q],     acc[g][1]);
                acc[g][1] = fma2(h1.y, wg[g][2 * q + 1], acc[g][1]);
            }
        }

        float sv[4][2];
#pragma unroll
        for (int g = 0; g < 4; g++)
#pragma unroll
            for (int bb = 0; bb < 2; bb++) {
                float lo, hi; unpack2(acc[g][bb], lo, hi);
                sv[g][bb] = lo + hi;
            }
        u64 P0 = pack2(sv[0][0], sv[1][0]);
        u64 Q0 = pack2(sv[2][0], sv[3][0]);
        u64 P1 = pack2(sv[0][1], sv[1][1]);
        u64 Q1 = pack2(sv[2][1], sv[3][1]);

        P0 = shfl_add2(P0, 8); P0 = shfl_add2(P0, 16);
        Q0 = shfl_add2(Q0, 8); Q0 = shfl_add2(Q0, 16);
        P1 = shfl_add2(P1, 8); P1 = shfl_add2(P1, 16);
        Q1 = shfl_add2(Q1, 8); Q1 = shfl_add2(Q1, 16);

        if (act) {
            u64 a01 = bl ? P1 : P0;
            u64 a23 = bl ? Q1 : Q0;
            float ai, af, ag, ao;
            unpack2(a01, ai, af);
            unpack2(a23, ag, ao);
            ai += cx_i; af += cx_f; ag += cx_g; ao += cx_o;
            float gi = fast_sig(ai);
            float gf = fast_sig(af);
            float gv = fast_tanh(ag);
            float go = fast_sig(ao);
            c = fmaf(gf, c, gi * gv);
            float h = go * fast_tanh(c);
            hs2[(s & 1) * HBUF + wroff] = h;
            __nv_bfloat16 hh, hl;
            bf16split(h, hh, hl);
            hop[(size_t)t * DH] = hh;
            lopw[(size_t)t * DH] = hl;
        }
        __syncthreads();
    }
}

// ---------------------------------------------------------------------------
// Final linear head on last timestep (reconstruct h = hi + lo).
// ---------------------------------------------------------------------------
__global__ __launch_bounds__(64) void head_kernel(
    const float* __restrict__ wl,      // (54, 128)
    const float* __restrict__ bl,      // (54,)
    float* __restrict__ out)           // (B, 54)
{
    const int b = blockIdx.x;
    __shared__ float hsm[DH];
    const int tid = threadIdx.x;
    for (int e = tid; e < DH; e += 64) {
        size_t idx = ((size_t)b * TT + (TT - 1)) * DH + e;
        hsm[e] = __bfloat162float(g_hbf_hi[idx]) + __bfloat162float(g_hbf_lo[idx]);
    }
    __syncthreads();
    if (tid < 54) {
        float acc = bl[tid];
#pragma unroll
        for (int k = 0; k < DH; k++) acc = fmaf(hsm[k], wl[tid * DH + k], acc);
        out[b * 54 + tid] = acc;
    }
}

// ---------------------------------------------------------------------------
extern "C" void kernel_launch(void* const* d_in, const int* in_sizes, int n_in,
                              void* d_out, int out_size)
{
    (void)in_sizes; (void)n_in; (void)out_size;
    const float* x      = (const float*)d_in[0];
    const float* w_ih_f = (const float*)d_in[1];
    const float* w_ih_r = (const float*)d_in[2];
    const float* w_hh   = (const float*)d_in[3];
    const float* b_ih   = (const float*)d_in[4];
    const float* b_hh   = (const float*)d_in[5];
    const float* w_lin  = (const float*)d_in[6];
    const float* b_lin  = (const float*)d_in[7];
    float* out = (float*)d_out;

    cudaFuncSetAttribute(gemm_mma_kernel,
                         cudaFuncAttributeMaxDynamicSharedMemorySize, MM_SMEM);

    dim3 grid0(BB, 2, 4);
    dim3 gridM(BB, 2, 8);     // (batch, dir, t-chunk of 128)
    dim3 gridR(BB / 2, 2);

    // Prep: W_ih bf16 split (tiny)
    wsplit_kernel<<<6, 256>>>(w_ih_r);

    // Layer 0
    gemm0_kernel<<<grid0, 256>>>(x, w_ih_f, b_ih, b_hh);
    lstm_recur_kernel<<<gridR, 256>>>(w_hh, 0);

    // Layers 1..3 (HMMA input projections)
    for (int l = 1; l < 4; l++) {
        gemm_mma_kernel<<<gridM, 256, MM_SMEM>>>(b_ih, b_hh, l);
        lstm_recur_kernel<<<gridR, 256>>>(w_hh, l);
    }

    // Head
    head_kernel<<<BB, 64>>>(w_lin, b_lin, out);
}

// round 14
// speedup vs baseline: 1.2528x; 1.2528x over previous
#include <cuda_runtime.h>
#include <cuda_bf16.h>
#include <math.h>

// Problem constants
#define BB   256
#define TT   1000
#define HH   64
#define GG   256   // 4*H
#define DIN  22
#define DH   128   // 2*H

typedef unsigned int u32;
typedef unsigned long long u64;

// Scratch (device globals; no runtime allocation allowed)
__device__ float g_xw[(size_t)2 * BB * TT * GG];            // [dir][b][t][g]
__device__ __nv_bfloat16 g_hbf_hi[(size_t)BB * TT * DH];    // h split hi [b][t][d]
__device__ __nv_bfloat16 g_hbf_lo[(size_t)BB * TT * DH];    // h split lo
// W_ih fragments: [ld 6][gate-octet 32][ks 8][lane 32] = {bh0,bh1,bl0,bl1}
__device__ uint4 g_wfrag[(size_t)6 * 32 * 8 * 32];

// ---- packed f32x2 helpers ----
__device__ __forceinline__ u64 pack2(float lo, float hi) {
    u64 r; asm("mov.b64 %0, {%1, %2};" : "=l"(r) : "f"(lo), "f"(hi)); return r;
}
__device__ __forceinline__ void unpack2(u64 v, float& lo, float& hi) {
    asm("mov.b64 {%0, %1}, %2;" : "=f"(lo), "=f"(hi) : "l"(v));
}
__device__ __forceinline__ u64 fma2(u64 a, u64 b, u64 c) {
    u64 d; asm("fma.rn.f32x2 %0, %1, %2, %3;" : "=l"(d) : "l"(a), "l"(b), "l"(c));
    return d;
}
__device__ __forceinline__ u64 shfl_add2(u64 v, int m) {
    float lo, hi; unpack2(v, lo, hi);
    float lo2 = __shfl_xor_sync(0xFFFFFFFFu, lo, m);
    float hi2 = __shfl_xor_sync(0xFFFFFFFFu, hi, m);
    return pack2(lo + lo2, hi + hi2);
}

__device__ __forceinline__ float ex2a(float x) {
    float y; asm("ex2.approx.f32 %0, %1;" : "=f"(y) : "f"(x)); return y;
}
__device__ __forceinline__ float rcpa(float x) {
    float y; asm("rcp.approx.f32 %0, %1;" : "=f"(y) : "f"(x)); return y;
}
#define L2E  1.4426950408889634f
__device__ __forceinline__ float fast_sig(float x) {
    return rcpa(1.0f + ex2a(-L2E * x));
}
__device__ __forceinline__ float fast_tanh(float x) {
    return fmaf(2.0f, rcpa(1.0f + ex2a(-2.0f * L2E * x)), -1.0f);
}
__device__ __forceinline__ void bf16split(float f, __nv_bfloat16& h, __nv_bfloat16& l) {
    h = __float2bfloat16(f);
    l = __float2bfloat16(f - __bfloat162float(h));
}
__device__ __forceinline__ u32 packbf(__nv_bfloat16 a, __nv_bfloat16 b) {
    __nv_bfloat162 t = __halves2bfloat162(a, b);
    return *(u32*)&t;
}
__device__ __forceinline__ u32 smem_addr_u32(const void* p) {
    u32 a;
    asm("{ .reg .u64 t; cvta.to.shared.u64 t, %1; cvt.u32.u64 %0, t; }"
        : "=r"(a) : "l"(p));
    return a;
}

// ---- bf16 HMMA m16n8k16 (baseline PTX, sm_80+) ----
__device__ __forceinline__ void mma16816(
    float& d0, float& d1, float& d2, float& d3,
    u32 a0, u32 a1, u32 a2, u32 a3, u32 b0, u32 b1)
{
    asm volatile(
        "mma.sync.aligned.m16n8k16.row.col.f32.bf16.bf16.f32 "
        "{%0,%1,%2,%3}, {%4,%5,%6,%7}, {%8,%9}, {%0,%1,%2,%3};"
        : "+f"(d0), "+f"(d1), "+f"(d2), "+f"(d3)
        : "r"(a0), "r"(a1), "r"(a2), "r"(a3), "r"(b0), "r"(b1));
}
// ldmatrix x4 (baseline PTX, sm_75+)
__device__ __forceinline__ void ldsm4(u32 addr, u32& r0, u32& r1, u32& r2, u32& r3) {
    asm volatile(
        "ldmatrix.sync.aligned.m8n8.x4.shared.b16 {%0,%1,%2,%3}, [%4];"
        : "=r"(r0), "=r"(r1), "=r"(r2), "=r"(r3) : "r"(addr));
}

// ---------------------------------------------------------------------------
// W_ih fragment prep: pack bf16 hi/lo B-fragments in lane order.
// grid 6 (ld), 256 threads. Entry e: go=e>>8, ks=(e>>5)&7, lane=e&31.
// ---------------------------------------------------------------------------
__global__ __launch_bounds__(256) void wsplit_kernel(
    const float* __restrict__ w)       // (3, 2, 256, 128)
{
    const int ld = blockIdx.x;
    const float* src = w + (size_t)ld * GG * DH;
    uint4* dst = g_wfrag + (size_t)ld * 32 * 8 * 32;
    for (int e = threadIdx.x; e < 8192; e += 256) {
        int go = e >> 8, ks = (e >> 5) & 7, lane = e & 31;
        int n = go * 8 + (lane >> 2);
        int t4 = lane & 3;
        int k0 = ks * 16 + 2 * t4;
        const float* row = src + (size_t)n * DH;
        __nv_bfloat16 h00, l00, h01, l01, h10, l10, h11, l11;
        bf16split(row[k0],     h00, l00);
        bf16split(row[k0 + 1], h01, l01);
        bf16split(row[k0 + 8], h10, l10);
        bf16split(row[k0 + 9], h11, l11);
        dst[e] = make_uint4(packbf(h00, h01), packbf(h10, h11),
                            packbf(l00, l01), packbf(l10, l11));
    }
}

// ---------------------------------------------------------------------------
// Layer-0 input projection, t-split x4. grid (B, 2, 4), 256 threads. (fp32)
// ---------------------------------------------------------------------------
__global__ __launch_bounds__(256) void gemm0_kernel(
    const float* __restrict__ x,       // (B, 22, T)
    const float* __restrict__ w,       // (2, 256, 22)
    const float* __restrict__ bih,     // (4, 2, 256)
    const float* __restrict__ bhh)     // (4, 2, 256)
{
    const int b = blockIdx.x, dir = blockIdx.y, tch = blockIdx.z;
    const int g = threadIdx.x;
    __shared__ float xs[DIN][16];

    float wr[DIN];
#pragma unroll
    for (int d = 0; d < DIN; d++) wr[d] = w[(dir * GG + g) * DIN + d];
    const float bias = bih[dir * GG + g] + bhh[dir * GG + g];

    const float* xb = x + (size_t)b * DIN * TT;
    float* out = g_xw + ((size_t)(dir * BB + b)) * TT * GG;

    const int tbase = tch * 256;
    const int tend  = (tbase + 256 < TT) ? (tbase + 256) : TT;

    for (int tc = tbase; tc < tend; tc += 16) {
        for (int e = threadIdx.x; e < DIN * 16; e += 256) {
            int d = e >> 4, tt = e & 15;
            int t = tc + tt;
            xs[d][tt] = (t < TT) ? xb[d * TT + t] : 0.0f;
        }
        __syncthreads();
        float acc[16];
#pragma unroll
        for (int tt = 0; tt < 16; tt++) acc[tt] = bias;
#pragma unroll
        for (int d = 0; d < DIN; d++) {
            float wd = wr[d];
#pragma unroll
            for (int tt = 0; tt < 16; tt++) acc[tt] = fmaf(wd, xs[d][tt], acc[tt]);
        }
#pragma unroll
        for (int tt = 0; tt < 16; tt++) {
            int t = tc + tt;
            if (t < tend) out[(size_t)t * GG + g] = acc[tt];
        }
        __syncthreads();
    }
}

// ---------------------------------------------------------------------------
// Layers 1..3 input projection via bf16-split HMMA, ldmatrix + packed W.
// grid (B, 2, 8): (batch, dir, t-chunk of 128). 256 threads, 2 blocks/SM.
// A = x (smem, hi/lo, ldmatrix.x4), B = W (global fragment table, LDG.128).
// D = Xhi*Whi + Xlo*Whi + Xhi*Wlo. Warp tile 32t x 32g, 4 iterations.
// ---------------------------------------------------------------------------
#define XROWB 272                      // bytes per t-row (128 bf16 + 8 pad)
#define OFF_XL2 (128 * XROWB)          // 34816
#define OFF_BI2 (2 * 128 * XROWB)      // 69632
#define MM_SMEM (OFF_BI2 + GG * 4)     // 70656 B

__global__ __launch_bounds__(256, 2) void gemm_mma_kernel(
    const float* __restrict__ bih,
    const float* __restrict__ bhh,
    int layer)
{
    extern __shared__ char smb[];
    float* bsm = (float*)(smb + OFF_BI2);

    const int b = blockIdx.x, dir = blockIdx.y, tch = blockIdx.z;
    const int tid = threadIdx.x;
    const int w8 = tid >> 5, lane = tid & 31;
    const int tw = w8 & 1;             // t subgroup (0..1)
    const int gw = w8 >> 1;            // gate subgroup (0..3)
    const int g4 = lane >> 2;          // groupID (0..7)
    const int t4 = lane & 3;           // thread-in-group

    const int tb = tch * 128;          // global t base of this chunk

    // Stage bias
    if (tid < GG)
        bsm[tid] = bih[(layer * 2 + dir) * GG + tid]
                 + bhh[(layer * 2 + dir) * GG + tid];

    // Stage X chunk (hi/lo) into smem rows [t][128 halves], 272B stride
    {
        const uint4* hip = (const uint4*)(g_hbf_hi + (size_t)b * TT * DH);
        const uint4* lop = (const uint4*)(g_hbf_lo + (size_t)b * TT * DH);
        for (int e = tid; e < 2048; e += 256) {
            int r = e >> 4, q = e & 15;
            int t = tb + r;
            uint4 vh, vl;
            if (t < TT) {
                vh = hip[t * 16 + q];
                vl = lop[t * 16 + q];
            } else {
                vh = make_uint4(0, 0, 0, 0); vl = vh;
            }
            *(uint4*)(smb + r * XROWB + q * 16) = vh;
            *(uint4*)(smb + OFF_XL2 + r * XROWB + q * 16) = vl;
        }
    }
    __syncthreads();

    const int ld = (layer - 1) * 2 + dir;
    const uint4* wfl = g_wfrag + (size_t)ld * 32 * 8 * 32;
    float* outp = g_xw + ((size_t)(dir * BB + b)) * TT * GG;

    // ldmatrix per-lane addressing: lanes 0-7 -> m0 rows, 8-15 -> m1 (+8 rows),
    // 16-23 -> m2 (+16B col), 24-31 -> m3 (+8 rows, +16B col)
    const u32 sm0 = smem_addr_u32(smb);
    const int arow = (lane & 7) + ((lane >> 3) & 1) * 8;
    const int acol = (lane >> 4) * 16;

#pragma unroll
    for (int it = 0; it < 4; it++) {
        const int tloc  = (it >> 1) * 64 + tw * 32;          // local t base
        const int gbase = (it & 1) * 128 + gw * 32;          // gate base
        const int gob   = (gbase >> 3);                      // gate-octet base

        float acc[2][4][4];
#pragma unroll
        for (int mt = 0; mt < 2; mt++)
#pragma unroll
            for (int nt = 0; nt < 4; nt++)
#pragma unroll
                for (int i = 0; i < 4; i++) acc[mt][nt][i] = 0.0f;

        const u32 abase0 = sm0 + (u32)((tloc + arow) * XROWB + acol);
        const u32 abase1 = abase0 + 16 * XROWB;

#pragma unroll
        for (int ks = 0; ks < 8; ks++) {
            // A fragments (hi/lo) via ldmatrix.x4
            u32 ah[2][4], al[2][4];
            ldsm4(abase0 + ks * 32,           ah[0][0], ah[0][1], ah[0][2], ah[0][3]);
            ldsm4(abase1 + ks * 32,           ah[1][0], ah[1][1], ah[1][2], ah[1][3]);
            ldsm4(abase0 + OFF_XL2 + ks * 32, al[0][0], al[0][1], al[0][2], al[0][3]);
            ldsm4(abase1 + OFF_XL2 + ks * 32, al[1][0], al[1][1], al[1][2], al[1][3]);

#pragma unroll
            for (int nt = 0; nt < 4; nt++) {
                uint4 wv = wfl[(size_t)((gob + nt) * 8 + ks) * 32 + lane];
#pragma unroll
                for (int mt = 0; mt < 2; mt++) {
                    mma16816(acc[mt][nt][0], acc[mt][nt][1],
                             acc[mt][nt][2], acc[mt][nt][3],
                             ah[mt][0], ah[mt][1], ah[mt][2], ah[mt][3],
                             wv.x, wv.y);
                    mma16816(acc[mt][nt][0], acc[mt][nt][1],
                             acc[mt][nt][2], acc[mt][nt][3],
                             al[mt][0], al[mt][1], al[mt][2], al[mt][3],
                             wv.x, wv.y);
                    mma16816(acc[mt][nt][0], acc[mt][nt][1],
                             acc[mt][nt][2], acc[mt][nt][3],
                             ah[mt][0], ah[mt][1], ah[mt][2], ah[mt][3],
                             wv.z, wv.w);
                }
            }
        }

        // Store with bias. D layout: c0 (t=g4, n=2t4), c1 (n=2t4+1),
        // c2 (t=g4+8, n=2t4), c3 (n=2t4+1).
#pragma unroll
        for (int mt = 0; mt < 2; mt++) {
#pragma unroll
            for (int nt = 0; nt < 4; nt++) {
                int n0 = gbase + nt * 8 + 2 * t4;
                float b0 = bsm[n0], b1 = bsm[n0 + 1];
                int tr0 = tb + tloc + mt * 16 + g4;
                int tr1 = tr0 + 8;
                if (tr0 < TT)
                    *(float2*)(outp + (size_t)tr0 * GG + n0) =
                        make_float2(acc[mt][nt][0] + b0, acc[mt][nt][1] + b1);
                if (tr1 < TT)
                    *(float2*)(outp + (size_t)tr1 * GG + n0) =
                        make_float2(acc[mt][nt][2] + b0, acc[mt][nt][3] + b1);
            }
        }
    }
}

// ---------------------------------------------------------------------------
// Recurrent scan (FROZEN math from R9); output bf16 hi/lo split.
// grid (B/2, 2), 256 threads, 2 blocks/SM, one barrier per step.
// ---------------------------------------------------------------------------
#define HROW 80
#define HBUF (2 * HROW)

__global__ __launch_bounds__(256, 2) void lstm_recur_kernel(
    const float* __restrict__ whh,     // (4, 2, 256, 64)
    int layer)
{
    __shared__ __align__(16) float hs2[2 * HBUF];    // double buffer

    const int dir = blockIdx.y;
    const int b0 = blockIdx.x * 2;
    const int tid = threadIdx.x;
    const int lane = tid & 31;
    const int j_lo = lane & 7;
    const int ks   = lane >> 3;          // k-slice 0..3
    const int j_hi = tid >> 5;           // warp 0..7
    const int j    = j_hi * 8 + j_lo;    // hidden unit 0..63

    u64 wg[4][8];
    {
        const float* wb = whh + (size_t)(layer * 2 + dir) * GG * HH;
#pragma unroll
        for (int g = 0; g < 4; g++) {
            const float2* wr = (const float2*)(wb + ((size_t)(g * 64 + j)) * HH + ks * 16);
#pragma unroll
            for (int p = 0; p < 8; p++) {
                float2 v = wr[p];
                wg[g][p] = pack2(v.x, v.y);
            }
        }
    }

    for (int e = tid; e < 2 * HBUF; e += 256) hs2[e] = 0.0f;

    const bool act = (ks < 2);
    const int bl = ks & 1;
    const float* xwp = g_xw + ((size_t)(dir * BB + b0 + bl)) * TT * GG + j;
    __nv_bfloat16* hop = g_hbf_hi + ((size_t)(b0 + bl) * TT) * DH + dir * HH + j;
    __nv_bfloat16* lopw = g_hbf_lo + ((size_t)(b0 + bl) * TT) * DH + dir * HH + j;
    float c = 0.0f;

    __syncthreads();

    float nx_i = 0.f, nx_f = 0.f, nx_g = 0.f, nx_o = 0.f;
    if (act) {
        int t0 = dir ? (TT - 1) : 0;
        const float* xp = xwp + (size_t)t0 * GG;
        nx_i = xp[0]; nx_f = xp[64]; nx_g = xp[128]; nx_o = xp[192];
    }

    const int rdoff = ks * 20;
    const int wroff = bl * HROW + (j >> 4) * 20 + (j & 15);

    for (int s = 0; s < TT; s++) {
        const int t = dir ? (TT - 1 - s) : s;
        float cx_i = nx_i, cx_f = nx_f, cx_g = nx_g, cx_o = nx_o;
        if (act && s + 1 < TT) {
            int tn = dir ? (t - 1) : (t + 1);
            const float* xp = xwp + (size_t)tn * GG;
            nx_i = xp[0]; nx_f = xp[64]; nx_g = xp[128]; nx_o = xp[192];
        }

        const float* hb = hs2 + ((s + 1) & 1) * HBUF + rdoff;
        const ulonglong2* h0p = (const ulonglong2*)hb;
        const ulonglong2* h1p = (const ulonglong2*)(hb + HROW);

        u64 z = pack2(0.f, 0.f);
        u64 acc[4][2];
#pragma unroll
        for (int g = 0; g < 4; g++) { acc[g][0] = z; acc[g][1] = z; }

#pragma unroll
        for (int q = 0; q < 4; q++) {
            ulonglong2 h0 = h0p[q];
            ulonglong2 h1 = h1p[q];
#pragma unroll
            for (int g = 0; g < 4; g++) {
                acc[g][0] = fma2(h0.x, wg[g][2 * q],     acc[g][0]);
                acc[g][0] = fma2(h0.y, wg[g][2 * q + 1], acc[g][0]);
                acc[g][1] = fma2(h1.x, wg[g][2 * q],     acc[g][1]);
                acc[g][1] = fma2(h1.y, wg[g][2 * q + 1], acc[g][1]);
            }
        }

        float sv[4][2];
#pragma unroll
        for (int g = 0; g < 4; g++)
#pragma unroll
            for (int bb = 0; bb < 2; bb++) {
                float lo, hi; unpack2(acc[g][bb], lo, hi);
                sv[g][bb] = lo + hi;
            }
        u64 P0 = pack2(sv[0][0], sv[1][0]);
        u64 Q0 = pack2(sv[2][0], sv[3][0]);
        u64 P1 = pack2(sv[0][1], sv[1][1]);
        u64 Q1 = pack2(sv[2][1], sv[3][1]);

        P0 = shfl_add2(P0, 8); P0 = shfl_add2(P0, 16);
        Q0 = shfl_add2(Q0, 8); Q0 = shfl_add2(Q0, 16);
        P1 = shfl_add2(P1, 8); P1 = shfl_add2(P1, 16);
        Q1 = shfl_add2(Q1, 8); Q1 = shfl_add2(Q1, 16);

        if (act) {
            u64 a01 = bl ? P1 : P0;
            u64 a23 = bl ? Q1 : Q0;
            float ai, af, ag, ao;
            unpack2(a01, ai, af);
            unpack2(a23, ag, ao);
            ai += cx_i; af += cx_f; ag += cx_g; ao += cx_o;
            float gi = fast_sig(ai);
            float gf = fast_sig(af);
            float gv = fast_tanh(ag);
            float go = fast_sig(ao);
            c = fmaf(gf, c, gi * gv);
            float h = go * fast_tanh(c);
            hs2[(s & 1) * HBUF + wroff] = h;
            __nv_bfloat16 hh, hl;
            bf16split(h, hh, hl);
            hop[(size_t)t * DH] = hh;
            lopw[(size_t)t * DH] = hl;
        }
        __syncthreads();
    }
}

// ---------------------------------------------------------------------------
// Final linear head on last timestep (reconstruct h = hi + lo).
// ---------------------------------------------------------------------------
__global__ __launch_bounds__(64) void head_kernel(
    const float* __restrict__ wl,      // (54, 128)
    const float* __restrict__ bl,      // (54,)
    float* __restrict__ out)           // (B, 54)
{
    const int b = blockIdx.x;
    __shared__ float hsm[DH];
    const int tid = threadIdx.x;
    for (int e = tid; e < DH; e += 64) {
        size_t idx = ((size_t)b * TT + (TT - 1)) * DH + e;
        hsm[e] = __bfloat162float(g_hbf_hi[idx]) + __bfloat162float(g_hbf_lo[idx]);
    }
    __syncthreads();
    if (tid < 54) {
        float acc = bl[tid];
#pragma unroll
        for (int k = 0; k < DH; k++) acc = fmaf(hsm[k], wl[tid * DH + k], acc);
        out[b * 54 + tid] = acc;
    }
}

// ---------------------------------------------------------------------------
extern "C" void kernel_launch(void* const* d_in, const int* in_sizes, int n_in,
                              void* d_out, int out_size)
{
    (void)in_sizes; (void)n_in; (void)out_size;
    const float* x      = (const float*)d_in[0];
    const float* w_ih_f = (const float*)d_in[1];
    const float* w_ih_r = (const float*)d_in[2];
    const float* w_hh   = (const float*)d_in[3];
    const float* b_ih   = (const float*)d_in[4];
    const float* b_hh   = (const float*)d_in[5];
    const float* w_lin  = (const float*)d_in[6];
    const float* b_lin  = (const float*)d_in[7];
    float* out = (float*)d_out;

    cudaFuncSetAttribute(gemm_mma_kernel,
                         cudaFuncAttributeMaxDynamicSharedMemorySize, MM_SMEM);

    dim3 grid0(BB, 2, 4);
    dim3 gridM(BB, 2, 8);     // (batch, dir, t-chunk of 128)
    dim3 gridR(BB / 2, 2);

    // Prep: W_ih fragment table (tiny)
    wsplit_kernel<<<6, 256>>>(w_ih_r);

    // Layer 0
    gemm0_kernel<<<grid0, 256>>>(x, w_ih_f, b_ih, b_hh);
    lstm_recur_kernel<<<gridR, 256>>>(w_hh, 0);

    // Layers 1..3 (HMMA input projections)
    for (int l = 1; l < 4; l++) {
        gemm_mma_kernel<<<gridM, 256, MM_SMEM>>>(b_ih, b_hh, l);
        lstm_recur_kernel<<<gridR, 256>>>(w_hh, l);
    }

    // Head
    head_kernel<<<BB, 64>>>(w_lin, b_lin, out);
}